// round 9
// baseline (speedup 1.0000x reference)
#include <cuda_runtime.h>
#include <cstdint>

#define KC 512
#define DD 64
#define HW 4096
#define NVEC 131072
#define NTH 512                     // 16 warps: 0-7 scan k[0,256), 8-15 k[256,512)
#define VPC 256                     // vectors per chunk (2 threads per vector)
#define NCHUNK (NVEC / VPC)         // 512 chunks
#define GRID 128                    // 4 chunks per CTA, balanced
#define SMEM_BYTES (KC * DD * 4 + KC * 4 + VPC * 4)

typedef unsigned long long u64;
typedef unsigned int u32;

__device__ __forceinline__ u64 ffma2(u64 a, u64 b, u64 c) {
    u64 d;
    asm("fma.rn.f32x2 %0, %1, %2, %3;" : "=l"(d) : "l"(a), "l"(b), "l"(c));
    return d;
}
__device__ __forceinline__ u64 pk(float lo, float hi) {
    u64 d;
    asm("mov.b64 %0, {%1, %2};" : "=l"(d) : "f"(lo), "f"(hi));
    return d;
}
__device__ __forceinline__ void unpack2(u64 a, float& lo, float& hi) {
    asm("mov.b64 {%0, %1}, %2;" : "=f"(lo), "=f"(hi) : "l"(a));
}

// Quarter-row FMA block, single vector: pairs 8q..8q+7; chain c consumes
// pairs == c (mod 4) ascending -- byte-identical per-(vector,k) accumulation
// order to rounds 1-3 (rel_err was exactly 0.0).
#define QFMA(bp, q)                                                         \
    do {                                                                    \
        a0 = ffma2(x2[8*(q)+0], (bp)[0].x, a0);                             \
        a1 = ffma2(x2[8*(q)+1], (bp)[0].y, a1);                             \
        a2 = ffma2(x2[8*(q)+2], (bp)[1].x, a2);                             \
        a3 = ffma2(x2[8*(q)+3], (bp)[1].y, a3);                             \
        a0 = ffma2(x2[8*(q)+4], (bp)[2].x, a0);                             \
        a1 = ffma2(x2[8*(q)+5], (bp)[2].y, a1);                             \
        a2 = ffma2(x2[8*(q)+6], (bp)[3].x, a2);                             \
        a3 = ffma2(x2[8*(q)+7], (bp)[3].y, a3);                             \
    } while (0)

#define PREF(bp, src)                                                       \
    do {                                                                    \
        (bp)[0] = (src)[0]; (bp)[1] = (src)[1];                             \
        (bp)[2] = (src)[2]; (bp)[3] = (src)[3];                             \
    } while (0)

// Scalar tree identical to rounds 1-3 (bit-exact).
__device__ __forceinline__ float tree8(u64 a0, u64 a1, u64 a2, u64 a3) {
    float f0, f1, f2, f3, f4, f5, f6, f7;
    unpack2(a0, f0, f1); unpack2(a1, f2, f3);
    unpack2(a2, f4, f5); unpack2(a3, f6, f7);
    return ((f0 + f1) + (f2 + f3)) + ((f4 + f5) + (f6 + f7));
}

__global__ void __launch_bounds__(NTH, 1)
vq_kernel(const float* __restrict__ ze, const float* __restrict__ cbg,
          float* __restrict__ out, int write2) {
    extern __shared__ float sm[];
    float* cb      = sm;                          // [512][64]
    float* cbsqr   = sm + KC * DD;                // [512]
    u32*   scratch = (u32*)(sm + KC * DD + KC);   // [256] key merge
    const int tid = threadIdx.x;

    {
        const float4* g4 = (const float4*)cbg;
        float4*       s4 = (float4*)cb;
        #pragma unroll
        for (int i = tid; i < KC * DD / 4; i += NTH) s4[i] = g4[i];
    }
    __syncthreads();
    for (int k = tid; k < KC; k += NTH) {
        const float* row = cb + k * DD;
        float s = 0.f;
        #pragma unroll
        for (int d = 0; d < DD; d++) s = fmaf(row[d], row[d], s);
        cbsqr[k] = s;
    }
    __syncthreads();

    const int P = tid >> 8;            // k-half: warps 0-7 -> 0, 8-15 -> 1
    const int v = tid & 255;           // vector index within chunk
    const int kbase = P << 8;          // 0 or 256
    const ulonglong2* c2p = (const ulonglong2*)cb + (size_t)kbase * 16;

    for (int chunk = blockIdx.x; chunk < NCHUNK; chunk += gridDim.x) {
        const int n = chunk * VPC + v;
        const int b = n >> 12;
        const int s = n & 4095;        // all v in a chunk share b (256 | 4096)
        const float* xp = ze + (size_t)b * (DD * HW) + s;

        // Full x per thread (both halves need all 64 dims); identical
        // sequential xsqr chain -> both threads of a pair get identical bits.
        u64 x2[DD / 2];
        float xsqr = 0.f;
        #pragma unroll
        for (int j = 0; j < DD / 2; j++) {
            float lo = xp[(size_t)(2 * j) * HW];
            float hi = xp[(size_t)(2 * j + 1) * HW];
            xsqr = fmaf(lo, lo, xsqr);
            xsqr = fmaf(hi, hi, xsqr);
            x2[j] = pk(lo, hi);
        }

        // u32 argmin key (R8-proven): dist > xsqr - 0.5 > 0, span < 2^23
        // => ((bits<<9)+k) - (base<<9) is order-exact mod 2^32 with
        // first-index tie-break in the low 9 bits. Same base for both halves.
        const u32 BS = ((u32)__float_as_int(fmaxf(xsqr - 0.5f, 0.0f))) << 9;
        u32 best = 0xFFFFFFFFu;

        ulonglong2 B0[4], B1[4];
        PREF(B0, c2p);                 // row kbase, quarter 0

        #pragma unroll 2
        for (int k = 0; k < KC / 2; k++) {
            const ulonglong2* r = c2p + k * 16;
            u64 a0 = 0, a1 = 0, a2 = 0, a3 = 0;
            PREF(B1, r + 4);   QFMA(B0, 0);
            PREF(B0, r + 8);   QFMA(B1, 1);
            PREF(B1, r + 12);  QFMA(B0, 2);
            PREF(B0, r + 16);  QFMA(B1, 3);   // last iter reads past row 511: in-bounds smem, unused

            float dot  = tree8(a0, a1, a2, a3);
            float dist = fmaf(-2.0f, dot, cbsqr[kbase + k] + xsqr);
            u32 key = (((u32)__float_as_int(dist)) << 9) + (u32)(kbase + k) - BS;
            best = min(best, key);
        }

        // Merge halves: global min key = exact first-index argmin over 512.
        if (P == 0) scratch[v] = best;
        __syncthreads();
        if (P == 1) scratch[v] = min(scratch[v], best);
        __syncthreads();
        const int kk = (int)(scratch[v] & 511u);

        // Scatter: each thread writes its 32-dim half of the winning code.
        const float4* code4 = (const float4*)(cb + kk * DD + P * 32);
        float* o1 = out + (size_t)b * (DD * HW) + (size_t)(P * 32) * HW + s;
        float* o2 = o1 + (size_t)NVEC * DD;
        #pragma unroll
        for (int q = 0; q < 8; q++) {
            float4 w = code4[q];
            o1[(size_t)(4 * q + 0) * HW] = w.x;
            o1[(size_t)(4 * q + 1) * HW] = w.y;
            o1[(size_t)(4 * q + 2) * HW] = w.z;
            o1[(size_t)(4 * q + 3) * HW] = w.w;
            if (write2) {
                o2[(size_t)(4 * q + 0) * HW] = w.x;
                o2[(size_t)(4 * q + 1) * HW] = w.y;
                o2[(size_t)(4 * q + 2) * HW] = w.z;
                o2[(size_t)(4 * q + 3) * HW] = w.w;
            }
        }
        __syncthreads();               // protect scratch before next chunk
    }
}

extern "C" void kernel_launch(void* const* d_in, const int* in_sizes, int n_in,
                              void* d_out, int out_size) {
    const float* ze  = (const float*)d_in[0];   // z_e_x [32,64,64,64] f32
    const float* cbg = (const float*)d_in[1];   // codebook [512,64] f32
    float* out = (float*)d_out;
    const int write2 = (out_size >= 2 * NVEC * DD) ? 1 : 0;
    cudaFuncSetAttribute(vq_kernel, cudaFuncAttributeMaxDynamicSharedMemorySize,
                         (int)SMEM_BYTES);
    vq_kernel<<<GRID, NTH, SMEM_BYTES>>>(ze, cbg, out, write2);
}

// round 10
// speedup vs baseline: 1.2807x; 1.2807x over previous
#include <cuda_runtime.h>
#include <cstdint>

#define KC 512
#define DD 64
#define HW 4096
#define NVEC 131072
#define NTH 256
#define NPT 2
#define CHUNKN (NTH * NPT)          // 512 vectors per chunk
#define NCHUNK (NVEC / CHUNKN)      // 256 chunks
#define GRID 128                    // 2 chunks per CTA, balanced
#define SMEM_BYTES (KC * DD * 4 + KC * 4)

typedef unsigned long long u64;
typedef unsigned int u32;

__device__ __forceinline__ u64 ffma2(u64 a, u64 b, u64 c) {
    u64 d;
    asm("fma.rn.f32x2 %0, %1, %2, %3;" : "=l"(d) : "l"(a), "l"(b), "l"(c));
    return d;
}
__device__ __forceinline__ u64 pk(float lo, float hi) {
    u64 d;
    asm("mov.b64 %0, {%1, %2};" : "=l"(d) : "f"(lo), "f"(hi));
    return d;
}
__device__ __forceinline__ void unpack2(u64 a, float& lo, float& hi) {
    asm("mov.b64 {%0, %1}, %2;" : "=f"(lo), "=f"(hi) : "l"(a));
}

// One 4-pair segment s for rows k (U) and k+1 (V), both vectors.
// Quad order maximizes RF-bank operand reuse: (xa*U)(xb*U)(xa*V)(xb*V).
// Chain j of each (vector,row) consumes pair 4s+j ascending s --
// byte-identical per-chain accumulation order to rounds 1-3 (rel_err 0.0).
#define QUAD(U, V, s)                                                       \
    do {                                                                    \
        a0 = ffma2(x2a[4*(s)+0], (U)[0], a0);                               \
        b0 = ffma2(x2b[4*(s)+0], (U)[0], b0);                               \
        c0 = ffma2(x2a[4*(s)+0], (V)[0], c0);                               \
        d0 = ffma2(x2b[4*(s)+0], (V)[0], d0);                               \
        a1 = ffma2(x2a[4*(s)+1], (U)[1], a1);                               \
        b1 = ffma2(x2b[4*(s)+1], (U)[1], b1);                               \
        c1 = ffma2(x2a[4*(s)+1], (V)[1], c1);                               \
        d1 = ffma2(x2b[4*(s)+1], (V)[1], d1);                               \
        a2 = ffma2(x2a[4*(s)+2], (U)[2], a2);                               \
        b2 = ffma2(x2b[4*(s)+2], (U)[2], b2);                               \
        c2 = ffma2(x2a[4*(s)+2], (V)[2], c2);                               \
        d2 = ffma2(x2b[4*(s)+2], (V)[2], d2);                               \
        a3 = ffma2(x2a[4*(s)+3], (U)[3], a3);                               \
        b3 = ffma2(x2b[4*(s)+3], (U)[3], b3);                               \
        c3 = ffma2(x2a[4*(s)+3], (V)[3], c3);                               \
        d3 = ffma2(x2b[4*(s)+3], (V)[3], d3);                               \
    } while (0)

// 4x LDS.64 prefetch of one 4-pair segment.
#define PREF4(B, src)                                                       \
    do {                                                                    \
        (B)[0] = (src)[0]; (B)[1] = (src)[1];                               \
        (B)[2] = (src)[2]; (B)[3] = (src)[3];                               \
    } while (0)

// Scalar tree identical to rounds 1-3 (bit-exact).
__device__ __forceinline__ float tree8(u64 a0, u64 a1, u64 a2, u64 a3) {
    float f0, f1, f2, f3, f4, f5, f6, f7;
    unpack2(a0, f0, f1); unpack2(a1, f2, f3);
    unpack2(a2, f4, f5); unpack2(a3, f6, f7);
    return ((f0 + f1) + (f2 + f3)) + ((f4 + f5) + (f6 + f7));
}

__global__ void __launch_bounds__(NTH, 1)
vq_kernel(const float* __restrict__ ze, const float* __restrict__ cbg,
          float* __restrict__ out, int write2) {
    extern __shared__ float sm[];
    float* cb    = sm;             // [512][64]
    float* cbsqr = sm + KC * DD;   // [512]
    const int tid = threadIdx.x;

    {
        const float4* g4 = (const float4*)cbg;
        float4*       s4 = (float4*)cb;
        #pragma unroll
        for (int i = tid; i < KC * DD / 4; i += NTH) s4[i] = g4[i];
    }
    __syncthreads();
    for (int k = tid; k < KC; k += NTH) {
        const float* row = cb + k * DD;
        float s = 0.f;
        #pragma unroll
        for (int d = 0; d < DD; d++) s = fmaf(row[d], row[d], s);
        cbsqr[k] = s;
    }
    __syncthreads();

    const u64* cbq = (const u64*)cb;  // f32x2 pairs, 32 per row

    for (int chunk = blockIdx.x; chunk < NCHUNK; chunk += gridDim.x) {
        const int n0 = chunk * CHUNKN + tid;
        const int b  = n0 >> 12;
        const int s0 = n0 & 4095;
        const float* xa = ze + (size_t)b * (DD * HW) + s0;
        const float* xb = xa + NTH;             // s0 + 256, same b

        u64 x2a[DD / 2], x2b[DD / 2];
        float xsqra = 0.f, xsqrb = 0.f;
        #pragma unroll
        for (int j = 0; j < DD / 2; j++) {
            float la = xa[(size_t)(2 * j) * HW];
            float ha = xa[(size_t)(2 * j + 1) * HW];
            xsqra = fmaf(la, la, xsqra);
            xsqra = fmaf(ha, ha, xsqra);
            x2a[j] = pk(la, ha);
            float lb = xb[(size_t)(2 * j) * HW];
            float hb = xb[(size_t)(2 * j + 1) * HW];
            xsqrb = fmaf(lb, lb, xsqrb);
            xsqrb = fmaf(hb, hb, xsqrb);
            x2b[j] = pk(lb, hb);
        }

        // u32 argmin keys (R8-proven exact): dist > xsqr - 0.5 > 0 and
        // bits(dist) - bits(base) < 2^23, so ((bits<<9)+k)-(base<<9) preserves
        // order with first-index tie-break (IMNMX on the idle alu pipe).
        const u32 BSa = ((u32)__float_as_int(fmaxf(xsqra - 0.5f, 0.0f))) << 9;
        const u32 BSb = ((u32)__float_as_int(fmaxf(xsqrb - 0.5f, 0.0f))) << 9;
        u32 bestA = 0xFFFFFFFFu, bestB = 0xFFFFFFFFu;

        // Double-buffered 4-pair segments for rows k (U*) and k+1 (V*).
        u64 U0[4], U1[4], V0[4], V1[4];
        PREF4(U0, cbq);            // row 0, pairs 0-3
        PREF4(V0, cbq + 32);       // row 1, pairs 0-3

        #pragma unroll 1
        for (int k = 0; k < KC; k += 2) {
            const u64* r  = cbq + k * 32;       // row k
            const u64* r1 = r + 32;             // row k+1
            u64 a0 = 0, a1 = 0, a2 = 0, a3 = 0;   // (A, k)
            u64 b0 = 0, b1 = 0, b2 = 0, b3 = 0;   // (B, k)
            u64 c0 = 0, c1 = 0, c2 = 0, c3 = 0;   // (A, k+1)
            u64 d0 = 0, d1 = 0, d2 = 0, d3 = 0;   // (B, k+1)

            PREF4(U1, r + 4);   PREF4(V1, r1 + 4);   QUAD(U0, V0, 0);
            PREF4(U0, r + 8);   PREF4(V0, r1 + 8);   QUAD(U1, V1, 1);
            PREF4(U1, r + 12);  PREF4(V1, r1 + 12);  QUAD(U0, V0, 2);
            PREF4(U0, r + 16);  PREF4(V0, r1 + 16);  QUAD(U1, V1, 3);
            PREF4(U1, r + 20);  PREF4(V1, r1 + 20);  QUAD(U0, V0, 4);
            PREF4(U0, r + 24);  PREF4(V0, r1 + 24);  QUAD(U1, V1, 5);
            PREF4(U1, r + 28);  PREF4(V1, r1 + 28);  QUAD(U0, V0, 6);
            // Prefetch next k-pair's first segments (k=510 reads the cbsqr
            // region: in-bounds shared memory, values unused).
            PREF4(U0, r + 64);  PREF4(V0, r1 + 64);  QUAD(U1, V1, 7);

            const float ck  = cbsqr[k];
            const float ck1 = cbsqr[k + 1];
            // Trees + dist: byte-identical sequences to rounds 1-3.
            float dot, dist;
            dot  = tree8(a0, a1, a2, a3);
            dist = fmaf(-2.0f, dot, ck + xsqra);
            bestA = min(bestA, (((u32)__float_as_int(dist)) << 9) + (u32)k - BSa);
            dot  = tree8(b0, b1, b2, b3);
            dist = fmaf(-2.0f, dot, ck + xsqrb);
            bestB = min(bestB, (((u32)__float_as_int(dist)) << 9) + (u32)k - BSb);
            dot  = tree8(c0, c1, c2, c3);
            dist = fmaf(-2.0f, dot, ck1 + xsqra);
            bestA = min(bestA, (((u32)__float_as_int(dist)) << 9) + (u32)(k + 1) - BSa);
            dot  = tree8(d0, d1, d2, d3);
            dist = fmaf(-2.0f, dot, ck1 + xsqrb);
            bestB = min(bestB, (((u32)__float_as_int(dist)) << 9) + (u32)(k + 1) - BSb);
        }

        const int bka = (int)(bestA & 511u);
        const int bkb = (int)(bestB & 511u);

        #pragma unroll
        for (int v = 0; v < NPT; v++) {
            const int   kk = (v == 0) ? bka : bkb;
            const int   ss = s0 + v * NTH;
            const float4* code4 = (const float4*)(cb + kk * DD);
            float* o1 = out + (size_t)b * (DD * HW) + ss;
            float* o2 = o1 + (size_t)NVEC * DD;
            #pragma unroll
            for (int q = 0; q < DD / 4; q++) {
                float4 w = code4[q];
                o1[(size_t)(4 * q + 0) * HW] = w.x;
                o1[(size_t)(4 * q + 1) * HW] = w.y;
                o1[(size_t)(4 * q + 2) * HW] = w.z;
                o1[(size_t)(4 * q + 3) * HW] = w.w;
                if (write2) {
                    o2[(size_t)(4 * q + 0) * HW] = w.x;
                    o2[(size_t)(4 * q + 1) * HW] = w.y;
                    o2[(size_t)(4 * q + 2) * HW] = w.z;
                    o2[(size_t)(4 * q + 3) * HW] = w.w;
                }
            }
        }
    }
}

extern "C" void kernel_launch(void* const* d_in, const int* in_sizes, int n_in,
                              void* d_out, int out_size) {
    const float* ze  = (const float*)d_in[0];   // z_e_x [32,64,64,64] f32
    const float* cbg = (const float*)d_in[1];   // codebook [512,64] f32
    float* out = (float*)d_out;
    const int write2 = (out_size >= 2 * NVEC * DD) ? 1 : 0;
    cudaFuncSetAttribute(vq_kernel, cudaFuncAttributeMaxDynamicSharedMemorySize,
                         (int)SMEM_BYTES);
    vq_kernel<<<GRID, NTH, SMEM_BYTES>>>(ze, cbg, out, write2);
}